// round 15
// baseline (speedup 1.0000x reference)
#include <cuda_runtime.h>
#include <cuda_bf16.h>
#include <cuda_fp16.h>
#include <math.h>
#include <stdint.h>

#define NC      128       // persistent CTAs; CTA owns hidden slice j0 = bid*8
#define TSTEPS  512

// ---------------- scratch (__device__ globals; no runtime allocation) ------
__device__ float g_xi[(size_t)512 * 128 * 3072];     // [T][B][3H]
__device__ __half g_xh[(size_t)128 * 512 * 512];     // x fp16
__device__ __half g_wih[(size_t)512 * 3072];         // Wi fp16
__device__ __half g_hf[2][128 * 1024];               // h fp16 (ping-pong)
__device__ unsigned g_bard[64];                      // [0]=domain0, [32]=domain1

// ---------------- recurrence SMEM layout (dynamic, bytes) -------------------
// ws: W fragments fp16 (single term): [ks64][gate3][lane32][reg2] u32 = 48KB
// A staging: per-warp private, 4 bufs x (16 rows x 272B) = 17408 B/warp
#define WS_OFF     0
#define A_OFF      49152
#define A_BUF_SZ   4352          // 16 rows * 272B
#define A_WARP_SZ  17408         // 4 bufs
#define SMEM_TOTAL (49152 + 8 * 17408)   // 188416

// ---------------- xi mma SMEM layout (bytes) --------------------------------
#define XA_OFF   0
#define XA_BUFSZ 18432           // 128*144
#define XB_OFF   36864
#define XB_BUFSZ 9216            // 64*144
#define SMEM_XI  55296

// ---------------- PTX helpers ------------------------------------------------
__device__ __forceinline__ void mma_f16(float* c, const uint32_t* a,
                                        uint32_t b0, uint32_t b1) {
    asm volatile(
        "mma.sync.aligned.m16n8k16.row.col.f32.f16.f16.f32 "
        "{%0,%1,%2,%3}, {%4,%5,%6,%7}, {%8,%9}, {%0,%1,%2,%3};"
        : "+f"(c[0]), "+f"(c[1]), "+f"(c[2]), "+f"(c[3])
        : "r"(a[0]), "r"(a[1]), "r"(a[2]), "r"(a[3]), "r"(b0), "r"(b1));
}

__device__ __forceinline__ void ldmatrix_x4(uint32_t* a, uint32_t addr) {
    asm volatile(
        "ldmatrix.sync.aligned.m8n8.x4.shared.b16 {%0,%1,%2,%3}, [%4];"
        : "=r"(a[0]), "=r"(a[1]), "=r"(a[2]), "=r"(a[3]) : "r"(addr));
}

__device__ __forceinline__ void ldmatrix_x2t(uint32_t& b0, uint32_t& b1,
                                             uint32_t addr) {
    asm volatile(
        "ldmatrix.sync.aligned.m8n8.x2.trans.shared.b16 {%0,%1}, [%2];"
        : "=r"(b0), "=r"(b1) : "r"(addr));
}

__device__ __forceinline__ void cp16(uint32_t dst, const void* src) {
    asm volatile("cp.async.cg.shared.global [%0], [%1], 16;"
                 :: "r"(dst), "l"(src) : "memory");
}

// ---------------- fast gate math (ex2/rcp approx) ----------------------------
#define LOG2E 1.4426950408889634f
__device__ __forceinline__ float fexp2a(float x) {
    float r; asm("ex2.approx.f32 %0, %1;" : "=f"(r) : "f"(x)); return r;
}
__device__ __forceinline__ float frcpa(float x) {
    float r; asm("rcp.approx.f32 %0, %1;" : "=f"(r) : "f"(x)); return r;
}
__device__ __forceinline__ float fsigmoid(float x) {
    return frcpa(1.f + fexp2a(-x * LOG2E));
}
__device__ __forceinline__ float ftanh_(float x) {
    return 2.f * frcpa(1.f + fexp2a(-2.f * LOG2E * x)) - 1.f;
}

// ---------------- prep: x -> fp16 --------------------------------------------
__global__ __launch_bounds__(256) void split_x(const float* __restrict__ x)
{
    const size_t i = (size_t)blockIdx.x * 256 + threadIdx.x;
    g_xh[i] = __float2half_rn(x[i]);
}

// ---------------- prep: Wi -> fp16 -------------------------------------------
__global__ __launch_bounds__(256) void split_wi(const float* __restrict__ Wi)
{
    const size_t i = (size_t)blockIdx.x * 256 + threadIdx.x;
    g_wih[i] = __float2half_rn(Wi[i]);
}

// ---------------- xi = x @ Wi + bi  via mma.sync fp16 single-term ------------
// (unchanged, validated; tensor-issue-bound at ~0.67 ms)
__global__ __launch_bounds__(256, 3) void xi_mma(
    const float* __restrict__ bi, float* __restrict__ xi)
{
    extern __shared__ char sm[];
    const uint32_t su = (uint32_t)__cvta_generic_to_shared(sm);

    const int tid  = threadIdx.x;
    const int wid  = tid >> 5;
    const int lane = tid & 31;
    const int t    = blockIdx.y;
    const int n0   = blockIdx.x * 64;
    const int wm   = wid >> 1;
    const int wn   = wid & 1;

    float acc[2][4][4];
#pragma unroll
    for (int i = 0; i < 2; i++)
#pragma unroll
        for (int j = 0; j < 4; j++)
#pragma unroll
            for (int p = 0; p < 4; p++) acc[i][j][p] = 0.f;

    {
        const uint32_t ab = su + XA_OFF;
#pragma unroll
        for (int it = 0; it < 4; it++) {
            const int idx = tid + it * 256;
            const int r = idx >> 3, off = idx & 7;
            cp16(ab + r * 144 + off * 16,
                 &g_xh[((size_t)r * 512 + t) * 512 + off * 8]);
        }
#pragma unroll
        for (int it = 0; it < 2; it++) {
            const int idx = tid + it * 256;
            const int r = idx >> 3, off = idx & 7;
            cp16(su + XB_OFF + r * 144 + off * 16,
                 &g_wih[(size_t)r * 3072 + n0 + off * 8]);
        }
        asm volatile("cp.async.commit_group;" ::: "memory");
    }

#pragma unroll 1
    for (int c = 0; c < 8; c++) {
        asm volatile("cp.async.wait_group 0;" ::: "memory");
        __syncthreads();

        if (c < 7) {
            const int nb = (c + 1) & 1;
            const int kb = (c + 1) * 64;
            const uint32_t ab = su + XA_OFF + nb * XA_BUFSZ;
#pragma unroll
            for (int it = 0; it < 4; it++) {
                const int idx = tid + it * 256;
                const int r = idx >> 3, off = idx & 7;
                cp16(ab + r * 144 + off * 16,
                     &g_xh[((size_t)r * 512 + t) * 512 + kb + off * 8]);
            }
#pragma unroll
            for (int it = 0; it < 2; it++) {
                const int idx = tid + it * 256;
                const int r = idx >> 3, off = idx & 7;
                cp16(su + XB_OFF + nb * XB_BUFSZ + r * 144 + off * 16,
                     &g_wih[(size_t)(kb + r) * 3072 + n0 + off * 8]);
            }
            asm volatile("cp.async.commit_group;" ::: "memory");
        }

        const uint32_t abuf = su + XA_OFF + (c & 1) * XA_BUFSZ;
        const uint32_t bbuf = su + XB_OFF + (c & 1) * XB_BUFSZ;
#pragma unroll
        for (int kk = 0; kk < 4; kk++) {
            uint32_t a[2][4];
#pragma unroll
            for (int tile = 0; tile < 2; tile++) {
                const uint32_t aaddr = abuf
                    + (wm * 32 + tile * 16 + (lane & 15)) * 144
                    + (lane >> 4) * 16 + kk * 32;
                ldmatrix_x4(a[tile], aaddr);
            }
            uint32_t bf[4][2];
#pragma unroll
            for (int nt = 0; nt < 4; nt++) {
                const uint32_t baddr = bbuf
                    + (kk * 16 + (lane & 15)) * 144
                    + (wn * 32 + nt * 8) * 2;
                ldmatrix_x2t(bf[nt][0], bf[nt][1], baddr);
            }
#pragma unroll
            for (int tile = 0; tile < 2; tile++)
#pragma unroll
                for (int nt = 0; nt < 4; nt++)
                    mma_f16(acc[tile][nt], a[tile], bf[nt][0], bf[nt][1]);
        }
    }

    const int grp = lane >> 2;
    const int nlo = (lane & 3) * 2;
#pragma unroll
    for (int nt = 0; nt < 4; nt++) {
        const int n = n0 + wn * 32 + nt * 8 + nlo;
        const float2 bv = *reinterpret_cast<const float2*>(&bi[n]);
#pragma unroll
        for (int tile = 0; tile < 2; tile++) {
#pragma unroll
            for (int half = 0; half < 2; half++) {
                const int b = wm * 32 + tile * 16 + grp + half * 8;
                float2 o;
                o.x = acc[tile][nt][half * 2 + 0] + bv.x;
                o.y = acc[tile][nt][half * 2 + 1] + bv.y;
                *reinterpret_cast<float2*>(
                    &xi[((size_t)t * 128 + b) * 3072 + n]) = o;
            }
        }
    }
}

// ---------------- init: zero h buffer 0 + reset barrier counters ------------
__global__ void init_state()
{
    const int idx = blockIdx.x * 256 + threadIdx.x;   // < 131072
    g_hf[0][idx] = __float2half(0.f);
    if (idx < 64) g_bard[idx] = 0;
}

// ---------------- per-domain monotone-counter barrier ------------------------
// Named barrier (1+dom, 128 threads) replaces __syncthreads; the domain's
// 4 warps sync + one thread does release-add / acquire-poll on the domain's
// own counter (counters 128B apart -> no L2-line ping-pong between domains).
__device__ __forceinline__ void domain_barrier(int dom, unsigned target)
{
    asm volatile("bar.sync %0, 128;" :: "r"(1 + dom) : "memory");
    if (threadIdx.x == (unsigned)(dom * 128)) {
        asm volatile("red.release.gpu.global.add.u32 [%0], 1;"
                     :: "l"(&g_bard[dom * 32]) : "memory");
        unsigned v;
        do {
            asm volatile("ld.acquire.gpu.global.u32 %0, [%1];"
                         : "=r"(v) : "l"(&g_bard[dom * 32]) : "memory");
        } while (v < target);
    }
    asm volatile("bar.sync %0, 128;" :: "r"(1 + dom) : "memory");
}

// ---------------- persistent mma.sync GRU recurrence, DUAL-DOMAIN -----------
// 128 CTAs x 256 threads. CTA owns j-slice j0 = bid*8 (3 gates, N=24).
// Warps 0-3 = domain 0 (batch rows 0-63), warps 4-7 = domain 1 (rows 64-127).
// The two domains are INDEPENDENT recurrences with separate grid barriers,
// so one domain's barrier/fill stall is hidden by the other's mma stream on
// the same SMSPs. Domain 1 starts ~3us offset to de-phase the stalls.
// Warp-private 4-stage cp.async A staging; no __syncthreads in the loop.
__global__ __launch_bounds__(256, 1)
void gru_mma_persist(const float* __restrict__ Wh, const float* __restrict__ bh,
                     float* __restrict__ out)
{
    extern __shared__ char sm[];
    const uint32_t smem_u32 = (uint32_t)__cvta_generic_to_shared(sm);
    uint32_t* const ws = reinterpret_cast<uint32_t*>(sm + WS_OFF);

    const int tid  = threadIdx.x;
    const int wid  = tid >> 5;
    const int lane = tid & 31;
    const int bid  = blockIdx.x;
    const int j0   = bid * 8;
    const int dom  = wid >> 2;        // 0: rows 0-63, 1: rows 64-127

    // one-time: format Wh slice into fp16 mma B fragments (shared, read-only)
    for (int idx = tid; idx < 12288; idx += 256) {
        const int r    = idx & 1;
        const int l    = (idx >> 1) & 31;
        const int rest = idx >> 6;
        const int tt   = rest % 3;
        const int ks   = rest / 3;          // 0..63
        const int n = tt * 1024 + j0 + (l >> 2);
        const int k = ks * 16 + r * 8 + (l & 3) * 2;

        const __half e0 = __float2half_rn(Wh[(size_t)k * 3072 + n]);
        const __half e1 = __float2half_rn(Wh[(size_t)(k + 1) * 3072 + n]);
        ws[idx] = ((uint32_t)__half_as_ushort(e1) << 16)
                |  (uint32_t)__half_as_ushort(e0);
    }
    __syncthreads();   // only block-wide sync; before the loop

    // de-phase domain 1 by ~3us so the two domains' barrier stalls interleave
    if (dom == 1) {
#pragma unroll 1
        for (int i = 0; i < 6; i++) __nanosleep(512);
    }

    const int b0 = wid * 16 + (lane >> 2);          // rows b0, b0+8
    const int jb = j0 + (lane & 3) * 2;

    float bhv[3][2];
#pragma unroll
    for (int g = 0; g < 3; g++) {
        bhv[g][0] = bh[g * 1024 + jb];
        bhv[g][1] = bh[g * 1024 + jb + 1];
    }

    float hp[4];
#pragma unroll
    for (int p = 0; p < 4; p++) hp[p] = 0.f;

    const uint32_t awarp = smem_u32 + A_OFF + wid * A_WARP_SZ;
    const int arow = wid * 16;

#pragma unroll 1
    for (int t = 0; t < TSTEPS; t++) {
        const float* __restrict__ xi_t = g_xi + (size_t)t * 128 * 3072;
        const __half* __restrict__ hs = g_hf[t & 1];
        __half* __restrict__ hd = g_hf[(t + 1) & 1];

        // prologue FIRST: stage chunks 0..2 (h loads are the critical path)
#pragma unroll
        for (int pc = 0; pc < 3; pc++) {
            const uint32_t ab = awarp + pc * A_BUF_SZ;
#pragma unroll
            for (int it = 0; it < 8; it++) {
                const int idx = lane + it * 32;
                const int row = idx >> 4, off = idx & 15;
                cp16(ab + row * 272 + off * 16,
                     &hs[(arow + row) * 1024 + pc * 128 + off * 8]);
            }
            asm volatile("cp.async.commit_group;" ::: "memory");
        }

        // xi prefetch into registers (step-constant; hidden behind mainloop)
        float xiv[3][2][2];
#pragma unroll
        for (int g = 0; g < 3; g++)
#pragma unroll
            for (int rr = 0; rr < 2; rr++) {
                const float2 v = *reinterpret_cast<const float2*>(
                    &xi_t[(size_t)(b0 + rr * 8) * 3072 + g * 1024 + jb]);
                xiv[g][rr][0] = v.x; xiv[g][rr][1] = v.y;
            }

        float acc[3][4];
#pragma unroll
        for (int g = 0; g < 3; g++)
#pragma unroll
            for (int p = 0; p < 4; p++) acc[g][p] = 0.f;

#pragma unroll 1
        for (int c = 0; c < 8; c++) {
            if (c < 6)
                asm volatile("cp.async.wait_group 2;" ::: "memory");
            else if (c == 6)
                asm volatile("cp.async.wait_group 1;" ::: "memory");
            else
                asm volatile("cp.async.wait_group 0;" ::: "memory");
            __syncwarp();

            const uint32_t abuf = awarp + (c & 3) * A_BUF_SZ;
#pragma unroll
            for (int kk = 0; kk < 8; kk++) {
                uint32_t a[4];
                ldmatrix_x4(a, abuf + (lane & 15) * 272
                               + (lane >> 4) * 16 + kk * 32);
                const int ks = c * 8 + kk;
#pragma unroll
                for (int tt = 0; tt < 3; tt++) {
                    const uint32_t boff = smem_u32 + WS_OFF
                                        + (uint32_t)((ks * 3 + tt) * 256) + lane * 8;
                    uint32_t bh0, bh1;
                    asm("ld.shared.v2.u32 {%0,%1}, [%2];"
                        : "=r"(bh0), "=r"(bh1) : "r"(boff));
                    mma_f16(acc[tt], a, bh0, bh1);
                }
            }

            if (c < 5) {   // stage chunk c+3
                const uint32_t ab = awarp + ((c + 3) & 3) * A_BUF_SZ;
                const int kb = (c + 3) * 128;
#pragma unroll
                for (int it = 0; it < 8; it++) {
                    const int idx = lane + it * 32;
                    const int row = idx >> 4, off = idx & 15;
                    cp16(ab + row * 272 + off * 16,
                         &hs[(arow + row) * 1024 + kb + off * 8]);
                }
                asm volatile("cp.async.commit_group;" ::: "memory");
            }
        }

        // ---------------- gate epilogue (approx math, registers only) -------
#pragma unroll
        for (int rr = 0; rr < 2; rr++) {
            const int b = b0 + rr * 8;
            float hy2[2];
#pragma unroll
            for (int q = 0; q < 2; q++) {
                const int p = rr * 2 + q;
                const float hr = acc[0][p] + bhv[0][q];
                const float hz = acc[1][p] + bhv[1][q];
                const float hn = acc[2][p] + bhv[2][q];
                const float rg = fsigmoid(xiv[0][rr][q] + hr);
                const float zg = fsigmoid(xiv[1][rr][q] + hz);
                const float ng = ftanh_(xiv[2][rr][q] + rg * hn);
                const float hy = zg * ng + (1.f - zg) * hp[p];
                hp[p] = hy;
                hy2[q] = hy;
            }
            const __half e0 = __float2half_rn(hy2[0]);
            const __half e1 = __float2half_rn(hy2[1]);
            *reinterpret_cast<uint32_t*>(&hd[b * 1024 + jb]) =
                ((uint32_t)__half_as_ushort(e1) << 16)
                | (uint32_t)__half_as_ushort(e0);
            if (t == TSTEPS - 1) {
                float2 o; o.x = hy2[0]; o.y = hy2[1];
                *reinterpret_cast<float2*>(&out[b * 1024 + jb]) = o;
            }
        }

        if (t != TSTEPS - 1)
            domain_barrier(dom, (unsigned)(t + 1) * NC);
    }
}

// ---------------- launch ----------------------------------------------------
extern "C" void kernel_launch(void* const* d_in, const int* in_sizes, int n_in,
                              void* d_out, int out_size)
{
    const float* x  = (const float*)d_in[0];
    const float* Wi = (const float*)d_in[1];
    const float* bi = (const float*)d_in[2];
    const float* Wh = (const float*)d_in[3];
    const float* bh = (const float*)d_in[4];
    float* out = (float*)d_out;

    float* xi_ptr;
    cudaGetSymbolAddress((void**)&xi_ptr, g_xi);

    cudaFuncSetAttribute(gru_mma_persist,
                         cudaFuncAttributeMaxDynamicSharedMemorySize, SMEM_TOTAL);
    cudaFuncSetAttribute(xi_mma,
                         cudaFuncAttributeMaxDynamicSharedMemorySize, SMEM_XI);

    // prep: fp16 conversions
    split_x<<<131072, 256>>>(x);
    split_wi<<<6144, 256>>>(Wi);
    // xi = x @ Wi + bi on tensor cores (fp16 single-term, 3 CTAs/SM)
    xi_mma<<<dim3(48, 512), 256, SMEM_XI>>>(bi, xi_ptr);
    // zero h buffer + barrier counters
    init_state<<<512, 256>>>();
    // dual-domain persistent recurrence (independent batch halves)
    gru_mma_persist<<<NC, 256, SMEM_TOTAL>>>(Wh, bh, out);
}